// round 7
// baseline (speedup 1.0000x reference)
#include <cuda_runtime.h>
#include <math_constants.h>

#define BATCH     16
#define FRAMES    4000
#define BINS      257
#define HOP       128
#define G         22
#define NGROUPS   182
#define FRAMES_SH 25
#define OUT_LEN   512383
#define SWZ4(i)   ((i) ^ (((i) >> 3) & 7))
#define SWZ2(m)   ((m) ^ ((((m) >> 4) & 7) << 1))

// dynamic smem layout (bytes)
#define OFF_FR    0                 // 25*512*4 = 51200
#define OFF_WIN   51200             // 256 float2 (swizzled windowed pairs) = 2048
#define SMEM_BYTES 53248

__global__ __launch_bounds__(256, 4)
void istft_kernel(const float* __restrict__ xr,
                  const float* __restrict__ xi,
                  float* __restrict__ out)
{
    extern __shared__ __align__(16) char smem_raw[];
    float*  fr   = (float*)(smem_raw + OFF_FR);
    float2* ww2s = (float2*)(smem_raw + OFF_WIN);

    const int tid   = threadIdx.x;     // 256
    const int warp  = tid >> 5;
    const int lane  = tid & 31;
    const int group = blockIdx.x;
    const int batch = blockIdx.y;
    const int f0     = group * G;
    const int fstart = f0 - 3;

    // windowed pair table, swizzled: slot SWZ2(m) = (w[2m], w[2m+1]) / 768
    {
        int m = tid;                       // 0..255
        float w0 = (0.5f - 0.5f * cosf(2.0f * CUDART_PI_F * (float)(2 * m)     * (1.0f / 512.0f))) * (1.0f / 768.0f);
        float w1 = (0.5f - 0.5f * cosf(2.0f * CUDART_PI_F * (float)(2 * m + 1) * (1.0f / 512.0f))) * (1.0f / 768.0f);
        ww2s[SWZ2(m)] = make_float2(w0, w1);
    }
    __syncthreads();

    // ---- per-lane twiddles (frame-invariant) ----
    float pls, plc;   __sincosf(CUDART_PI_F * (float)lane * (1.0f / 256.0f), &pls, &plc);  // prerot base
    float s128, c128; __sincosf(CUDART_PI_F * (float)lane * (1.0f / 128.0f), &s128, &c128);
    float s64,  c64;  __sincosf(CUDART_PI_F * (float)lane * (1.0f / 64.0f),  &s64,  &c64);
    float s32,  c32;  __sincosf(CUDART_PI_F * (float)lane * (1.0f / 32.0f),  &s32,  &c32);
    float s16,  c16;  __sincosf(CUDART_PI_F * (float)(lane & 15) * (1.0f / 16.0f), &s16, &c16);
    float s8t,  c8t;  __sincosf(CUDART_PI_F * (float)(lane & 7)  * (1.0f / 8.0f),  &s8t, &c8t);
    float s4t,  c4t;  __sincosf(CUDART_PI_F * (float)(lane & 3)  * (1.0f / 4.0f),  &s4t, &c4t);

    const float R2 = 0.70710678118654752f;
    // prerot per-j constants e^{i*pi*j/8}
    const float C8[8] = {1.f, 0.92387953251128674f, 0.70710678118654752f, 0.38268343236508977f,
                         0.f, -0.38268343236508977f, -0.70710678118654752f, -0.92387953251128674f};
    const float S8[8] = {0.f, 0.38268343236508977f, 0.70710678118654752f, 0.92387953251128674f,
                         1.f, 0.92387953251128674f, 0.70710678118654752f, 0.38268343236508977f};

    const int rl = (int)(__brev((unsigned)lane) >> 27);     // rev5(lane)
    const int mBase = rl * 8;
    const int vx = ((rl >> 1) & 7) << 1;                    // SWZ2 xor term
    const size_t bbase = (size_t)batch * FRAMES;

    // branch-free constants for lane stages m = 16, 8, 4
    const float sg16 = (lane & 16) ? -1.f : 1.f;
    const float W16c = (lane & 16) ? c16 : 1.f, W16s = (lane & 16) ? s16 : 0.f;
    const float sg8  = (lane & 8)  ? -1.f : 1.f;
    const float W8c  = (lane & 8)  ? c8t : 1.f, W8s  = (lane & 8)  ? s8t : 0.f;
    const float sg4  = (lane & 4)  ? -1.f : 1.f;
    const float W4c  = (lane & 4)  ? c4t : 1.f, W4s  = (lane & 4)  ? s4t : 0.f;
    const bool hi2  = (lane & 2) != 0;
    const bool rot2 = (lane & 1) != 0;
    const bool hi1  = (lane & 1) != 0;

    for (int lf = warp; lf < FRAMES_SH; lf += 8) {
        const int f = fstart + lf;
        float2* row2 = (float2*)(fr + lf * 512);

        if (f < 0 || f >= FRAMES) {
            // zero this row (contributes nothing to OLA)
            #pragma unroll
            for (int q = 0; q < 8; q++) row2[q * 32 + lane] = make_float2(0.f, 0.f);
            continue;
        }

        const float* pre = xr + (bbase + f) * BINS;
        const float* pim = xi + (bbase + f) * BINS;

        float zr[8], zi[8];

        // Hermitian pack + pre-rotation, k = 32*j + lane (coalesced loads)
        #pragma unroll
        for (int j = 0; j < 8; j++) {
            int k  = 32 * j + lane;
            int km = 256 - k;
            float ar = pre[k];
            float br = pre[km];
            float ai, mi;
            if (k == 0) { ai = 0.f; mi = 0.f; }
            else        { ai = pim[k]; mi = pim[km]; }
            float er = ar + br, ei = ai - mi;    // bi = -mi
            float dr = ar - br, di = ai + mi;
            // prerot e^{i*pi*k/256} = (plc,pls) * (C8[j],S8[j])
            float pc = plc * C8[j] - pls * S8[j];
            float ps = plc * S8[j] + pls * C8[j];
            zr[j] = fmaf(-di, pc, fmaf(-dr, ps, er));   // er - dr*s - di*c
            zi[j] = fmaf(-di, ps, fmaf( dr, pc, ei));   // ei + dr*c - di*s
        }

        // ---- register stages (h = 128, 64, 32) ----
        {
            // w128[j] = e^{i*pi*lane/128} * e^{i*pi*j/4}
            float wc0 = c128,                wsn0 = s128;
            float wc1 = R2 * (c128 - s128),  wsn1 = R2 * (c128 + s128);
            float wc2 = -s128,               wsn2 = c128;
            float wc3 = -R2 * (c128 + s128), wsn3 = R2 * (c128 - s128);
            #define RB128(A,B,CC,SS) { float tr=zr[A]-zr[B], ti=zi[A]-zi[B]; \
                zr[A]+=zr[B]; zi[A]+=zi[B]; zr[B]=tr*(CC)-ti*(SS); zi[B]=tr*(SS)+ti*(CC); }
            RB128(0, 4, wc0, wsn0) RB128(1, 5, wc1, wsn1)
            RB128(2, 6, wc2, wsn2) RB128(3, 7, wc3, wsn3)
            #undef RB128
        }
        #define RB(A,B,CC,SS) { float tr=zr[A]-zr[B], ti=zi[A]-zi[B]; \
            zr[A]+=zr[B]; zi[A]+=zi[B]; zr[B]=tr*(CC)-ti*(SS); zi[B]=tr*(SS)+ti*(CC); }
        RB(0, 2, c64, s64)  RB(4, 6, c64, s64)
        RB(1, 3, -s64, c64) RB(5, 7, -s64, c64)
        RB(0, 1, c32, s32) RB(2, 3, c32, s32)
        RB(4, 5, c32, s32) RB(6, 7, c32, s32)
        #undef RB

        // ---- lane stages (branch-free): m = 16, 8, 4 ----
        #define LSTAGE(MASK, SG, WC, WS)                                        \
        {                                                                       \
            _Pragma("unroll")                                                   \
            for (int j = 0; j < 8; j++) {                                       \
                float orr = __shfl_xor_sync(0xffffffffu, zr[j], (MASK));        \
                float oii = __shfl_xor_sync(0xffffffffu, zi[j], (MASK));        \
                float tr = fmaf(zr[j], (SG), orr);                              \
                float ti = fmaf(zi[j], (SG), oii);                              \
                zr[j] = tr * (WC) - ti * (WS);                                  \
                zi[j] = tr * (WS) + ti * (WC);                                  \
            }                                                                   \
        }
        LSTAGE(16, sg16, W16c, W16s)
        LSTAGE(8,  sg8,  W8c,  W8s)
        LSTAGE(4,  sg4,  W4c,  W4s)
        #undef LSTAGE

        // m = 2: W = (rot2 ? i : 1) on hi half (predicated, no const regs)
        #pragma unroll
        for (int j = 0; j < 8; j++) {
            float orr = __shfl_xor_sync(0xffffffffu, zr[j], 2);
            float oii = __shfl_xor_sync(0xffffffffu, zi[j], 2);
            if (hi2) {
                float tr = orr - zr[j], ti = oii - zi[j];
                zr[j] = rot2 ? -ti : tr;
                zi[j] = rot2 ?  tr : ti;
            } else { zr[j] += orr; zi[j] += oii; }
        }
        // m = 1: W = 1
        #pragma unroll
        for (int j = 0; j < 8; j++) {
            float orr = __shfl_xor_sync(0xffffffffu, zr[j], 1);
            float oii = __shfl_xor_sync(0xffffffffu, zi[j], 1);
            if (hi1) { zr[j] = orr - zr[j]; zi[j] = oii - zi[j]; }
            else     { zr[j] += orr;        zi[j] += oii; }
        }

        // ---- direct bit-reversed windowed stores ----
        // position (lane, j) holds z[m], m = 8*rev5(lane) + rev3(j)
        {
            const int rev3[8] = {0, 4, 2, 6, 1, 5, 3, 7};
            #pragma unroll
            for (int j = 0; j < 8; j++) {
                int p2 = (mBase + rev3[j]) ^ vx;          // SWZ2(m)
                float2 w2 = ww2s[p2];
                row2[p2] = make_float2(zr[j] * w2.x, zi[j] * w2.y);
            }
        }
    }
    __syncthreads();

    // ---- gather overlap-add (window already applied; pure adds) ----
    const int sbase = f0 * HOP;
    int owned = G * HOP;
    if (OUT_LEN - sbase < owned) owned = OUT_LEN - sbase;
    const int n4 = (owned + 3) >> 2;
    float* outb = out + (size_t)batch * OUT_LEN;
    for (int t = tid; t < n4; t += 256) {
        int s0 = 4 * t;
        int qf = s0 >> 7;
        int r4 = (s0 & 127) >> 2;
        float a0 = 0.f, a1 = 0.f, a2 = 0.f, a3 = 0.f;
        #pragma unroll
        for (int d = 0; d < 4; d++) {
            int lf = qf - d + 3;
            if (lf < FRAMES_SH) {
                int i4 = r4 + (d << 5);
                int p4 = SWZ4(i4);
                float4 v = *(const float4*)&fr[lf * 512 + 4 * p4];
                a0 += v.x; a1 += v.y; a2 += v.z; a3 += v.w;
            }
        }
        int S = sbase + s0;
        if (S + 3 < OUT_LEN) {
            outb[S] = a0; outb[S + 1] = a1; outb[S + 2] = a2; outb[S + 3] = a3;
        } else {
            if (S     < OUT_LEN) outb[S]     = a0;
            if (S + 1 < OUT_LEN) outb[S + 1] = a1;
            if (S + 2 < OUT_LEN) outb[S + 2] = a2;
        }
    }
}

extern "C" void kernel_launch(void* const* d_in, const int* in_sizes, int n_in,
                              void* d_out, int out_size)
{
    const float* stft_real = (const float*)d_in[0];
    const float* stft_imag = (const float*)d_in[1];
    float* out = (float*)d_out;
    (void)in_sizes; (void)n_in; (void)out_size;

    cudaFuncSetAttribute(istft_kernel,
                         cudaFuncAttributeMaxDynamicSharedMemorySize, SMEM_BYTES);
    dim3 grid(NGROUPS, BATCH);
    istft_kernel<<<grid, 256, SMEM_BYTES>>>(stft_real, stft_imag, out);
}

// round 8
// speedup vs baseline: 1.1361x; 1.1361x over previous
#include <cuda_runtime.h>
#include <math_constants.h>

#define BATCH     16
#define FRAMES    4000
#define BINS      257
#define HOP       128
#define G         25
#define NGROUPS   160
#define FRAMES_SH 28
#define OUT_LEN   512383
#define SWZ4(i)   ((i) ^ (((i) >> 3) & 7))
#define SWZ2(m)   ((m) ^ ((((m) >> 4) & 7) << 1))

// dynamic smem layout (bytes)
#define OFF_FR    0                 // 28*512*4 = 57344
#define OFF_WIN   57344             // 256 float2 (swizzled windowed pairs) = 2048
#define OFF_PRT   59392             // 256 float2 prerot (cos, sin) = 2048
#define SMEM_BYTES 61440

__global__ __launch_bounds__(256, 3)
void istft_kernel(const float* __restrict__ xr,
                  const float* __restrict__ xi,
                  float* __restrict__ out)
{
    extern __shared__ __align__(16) char smem_raw[];
    float*  fr   = (float*)(smem_raw + OFF_FR);
    float2* ww2s = (float2*)(smem_raw + OFF_WIN);
    float2* prt  = (float2*)(smem_raw + OFF_PRT);

    const int tid   = threadIdx.x;     // 256
    const int warp  = tid >> 5;
    const int lane  = tid & 31;
    const int group = blockIdx.x;
    const int batch = blockIdx.y;
    const int f0     = group * G;
    const int fstart = f0 - 3;

    // windowed pair table, swizzled: slot SWZ2(m) = (w[2m], w[2m+1]) / 768
    {
        int m = tid;                       // 0..255
        float w0 = (0.5f - 0.5f * cosf(2.0f * CUDART_PI_F * (float)(2 * m)     * (1.0f / 512.0f))) * (1.0f / 768.0f);
        float w1 = (0.5f - 0.5f * cosf(2.0f * CUDART_PI_F * (float)(2 * m + 1) * (1.0f / 512.0f))) * (1.0f / 768.0f);
        ww2s[SWZ2(m)] = make_float2(w0, w1);
        // prerot: e^{i*pi*k/256}
        float s, c;
        sincosf(CUDART_PI_F * (float)m * (1.0f / 256.0f), &s, &c);
        prt[m] = make_float2(c, s);
    }
    if (group == 0)
        for (int i = tid; i < 3 * 512; i += 256) fr[i] = 0.f;
    __syncthreads();

    // ---- per-lane twiddles (frame-invariant) ----
    float s128, c128; __sincosf(CUDART_PI_F * (float)lane * (1.0f / 128.0f), &s128, &c128);
    float s64,  c64;  __sincosf(CUDART_PI_F * (float)lane * (1.0f / 64.0f),  &s64,  &c64);
    float s32,  c32;  __sincosf(CUDART_PI_F * (float)lane * (1.0f / 32.0f),  &s32,  &c32);
    float s16,  c16;  __sincosf(CUDART_PI_F * (float)(lane & 15) * (1.0f / 16.0f), &s16, &c16);
    float s8t,  c8t;  __sincosf(CUDART_PI_F * (float)(lane & 7)  * (1.0f / 8.0f),  &s8t, &c8t);
    float s4t,  c4t;  __sincosf(CUDART_PI_F * (float)(lane & 3)  * (1.0f / 4.0f),  &s4t, &c4t);

    const float R2 = 0.70710678118654752f;
    float w128c[4], w128s[4];
    w128c[0] = c128;               w128s[0] = s128;
    w128c[1] = R2 * (c128 - s128); w128s[1] = R2 * (c128 + s128);
    w128c[2] = -s128;              w128s[2] = c128;
    w128c[3] = -R2 * (c128 + s128); w128s[3] = R2 * (c128 - s128);

    const int rl = (int)(__brev((unsigned)lane) >> 27);     // rev5(lane)
    const int mBase = rl * 8;
    const int vx = ((rl >> 1) & 7) << 1;                    // SWZ2 xor term
    const int msrc = (32 - lane) & 31;                      // mirror shuffle source
    const size_t bbase = (size_t)batch * FRAMES;

    // branch-free constants for lane stages m = 16, 8, 4, 2
    const float sg16 = (lane & 16) ? -1.f : 1.f;
    const float W16c = (lane & 16) ? c16 : 1.f, W16s = (lane & 16) ? s16 : 0.f;
    const float sg8  = (lane & 8)  ? -1.f : 1.f;
    const float W8c  = (lane & 8)  ? c8t : 1.f, W8s  = (lane & 8)  ? s8t : 0.f;
    const float sg4  = (lane & 4)  ? -1.f : 1.f;
    const float W4c  = (lane & 4)  ? c4t : 1.f, W4s  = (lane & 4)  ? s4t : 0.f;
    const float sg2  = (lane & 2)  ? -1.f : 1.f;
    const bool  rot2 = (lane & 2) && (lane & 1);
    const float W2c  = rot2 ? 0.f : 1.f, W2s = rot2 ? 1.f : 0.f;
    const float sg1  = (lane & 1)  ? -1.f : 1.f;

    for (int lf = warp; lf < FRAMES_SH; lf += 8) {
        if (group == 0 && lf < 3) continue;
        const int f = fstart + lf;

        const float* pre = xr + (bbase + f) * BINS;
        const float* pim = xi + (bbase + f) * BINS;

        // ---- load each bin once: k = 32*j + lane (coalesced) ----
        float kr[8], ki[8];
        #pragma unroll
        for (int j = 0; j < 8; j++) {
            int k = 32 * j + lane;
            kr[j] = pre[k];
            ki[j] = pim[k];
        }
        const float pre256 = pre[256];   // uniform broadcast load

        float zr[8], zi[8];

        // Hermitian pack + pre-rotation; mirror X[256-k] via lane shuffle:
        //   k = 32j+lane (lane>0): X[256-k] = (lane (32-lane), reg 7-j)
        //   lane 0: X[256-32j] = reg 8-j (own), j=0 -> pre[256]
        #pragma unroll
        for (int j = 0; j < 8; j++) {
            float br = __shfl_sync(0xffffffffu, kr[7 - j], msrc);
            float mi = __shfl_sync(0xffffffffu, ki[7 - j], msrc);
            if (lane == 0) {
                br = (j == 0) ? pre256 : kr[j == 0 ? 0 : 8 - j];
                mi = (j == 0) ? 0.f    : ki[j == 0 ? 0 : 8 - j];
            }
            float ar = kr[j];
            float ai = (j == 0 && lane == 0) ? 0.f : ki[j];
            float er = ar + br, ei = ai - mi;    // bi = -mi
            float dr = ar - br, di = ai + mi;
            float2 t = prt[32 * j + lane];       // (cos, sin) pi*k/256
            zr[j] = fmaf(-di, t.x, fmaf(-dr, t.y, er));
            zi[j] = fmaf(-di, t.y, fmaf( dr, t.x, ei));
        }

        // ---- register stages (h = 128, 64, 32) ----
        #pragma unroll
        for (int j = 0; j < 4; j++) {
            float tr = zr[j] - zr[j + 4], ti = zi[j] - zi[j + 4];
            zr[j] += zr[j + 4]; zi[j] += zi[j + 4];
            zr[j + 4] = tr * w128c[j] - ti * w128s[j];
            zi[j + 4] = tr * w128s[j] + ti * w128c[j];
        }
        #define RB(A,B,CC,SS) { float tr=zr[A]-zr[B], ti=zi[A]-zi[B]; \
            zr[A]+=zr[B]; zi[A]+=zi[B]; zr[B]=tr*(CC)-ti*(SS); zi[B]=tr*(SS)+ti*(CC); }
        RB(0, 2, c64, s64)  RB(4, 6, c64, s64)
        RB(1, 3, -s64, c64) RB(5, 7, -s64, c64)
        RB(0, 1, c32, s32) RB(2, 3, c32, s32)
        RB(4, 5, c32, s32) RB(6, 7, c32, s32)
        #undef RB

        // ---- lane stages (branch-free): m = 16, 8, 4, 2 ----
        #define LSTAGE(MASK, SG, WC, WS)                                        \
        {                                                                       \
            _Pragma("unroll")                                                   \
            for (int j = 0; j < 8; j++) {                                       \
                float orr = __shfl_xor_sync(0xffffffffu, zr[j], (MASK));        \
                float oii = __shfl_xor_sync(0xffffffffu, zi[j], (MASK));        \
                float tr = fmaf(zr[j], (SG), orr);                              \
                float ti = fmaf(zi[j], (SG), oii);                              \
                zr[j] = tr * (WC) - ti * (WS);                                  \
                zi[j] = tr * (WS) + ti * (WC);                                  \
            }                                                                   \
        }
        LSTAGE(16, sg16, W16c, W16s)
        LSTAGE(8,  sg8,  W8c,  W8s)
        LSTAGE(4,  sg4,  W4c,  W4s)
        LSTAGE(2,  sg2,  W2c,  W2s)
        #undef LSTAGE
        // m = 1 (W = 1)
        #pragma unroll
        for (int j = 0; j < 8; j++) {
            float orr = __shfl_xor_sync(0xffffffffu, zr[j], 1);
            float oii = __shfl_xor_sync(0xffffffffu, zi[j], 1);
            zr[j] = fmaf(zr[j], sg1, orr);
            zi[j] = fmaf(zi[j], sg1, oii);
        }

        // ---- direct bit-reversed windowed stores ----
        // position (lane, j) holds z[m], m = 8*rev5(lane) + rev3(j)
        {
            float2* row2 = (float2*)(fr + lf * 512);
            const int rev3[8] = {0, 4, 2, 6, 1, 5, 3, 7};
            #pragma unroll
            for (int j = 0; j < 8; j++) {
                int p2 = (mBase + rev3[j]) ^ vx;          // SWZ2(m)
                float2 w2 = ww2s[p2];
                row2[p2] = make_float2(zr[j] * w2.x, zi[j] * w2.y);
            }
        }
    }
    __syncthreads();

    // ---- gather overlap-add (window already applied; pure adds) ----
    const int owned = (group == NGROUPS - 1) ? (G * HOP + 384) : (G * HOP);
    const int n4 = owned >> 2;
    const int sbase = f0 * HOP;
    float* outb = out + (size_t)batch * OUT_LEN;
    for (int t = tid; t < n4; t += 256) {
        int s0 = 4 * t;
        int qf = s0 >> 7;
        int r4 = (s0 & 127) >> 2;
        float a0 = 0.f, a1 = 0.f, a2 = 0.f, a3 = 0.f;
        #pragma unroll
        for (int d = 0; d < 4; d++) {
            int lf = qf - d + 3;
            if (lf < FRAMES_SH) {
                int i4 = r4 + (d << 5);
                int p4 = SWZ4(i4);
                float4 v = *(const float4*)&fr[lf * 512 + 4 * p4];
                a0 += v.x; a1 += v.y; a2 += v.z; a3 += v.w;
            }
        }
        int S = sbase + s0;
        if (S + 3 < OUT_LEN) {
            outb[S] = a0; outb[S + 1] = a1; outb[S + 2] = a2; outb[S + 3] = a3;
        } else {
            if (S     < OUT_LEN) outb[S]     = a0;
            if (S + 1 < OUT_LEN) outb[S + 1] = a1;
            if (S + 2 < OUT_LEN) outb[S + 2] = a2;
        }
    }
}

extern "C" void kernel_launch(void* const* d_in, const int* in_sizes, int n_in,
                              void* d_out, int out_size)
{
    const float* stft_real = (const float*)d_in[0];
    const float* stft_imag = (const float*)d_in[1];
    float* out = (float*)d_out;
    (void)in_sizes; (void)n_in; (void)out_size;

    cudaFuncSetAttribute(istft_kernel,
                         cudaFuncAttributeMaxDynamicSharedMemorySize, SMEM_BYTES);
    dim3 grid(NGROUPS, BATCH);
    istft_kernel<<<grid, 256, SMEM_BYTES>>>(stft_real, stft_imag, out);
}

// round 9
// speedup vs baseline: 1.2045x; 1.0602x over previous
#include <cuda_runtime.h>
#include <math_constants.h>

#define BATCH     16
#define FRAMES    4000
#define BINS      257
#define HOP       128
#define G         29
#define NGROUPS   138
#define FRAMES_SH 32
#define OUT_LEN   512383

// dynamic smem layout (bytes)
#define OFF_FR    0                 // 32*512*4 = 65536
#define OFF_WIN   65536             // 256 float2 natural windowed pairs = 2048
#define OFF_PRT   67584             // 256 float2 prerot = 2048
#define SMEM_BYTES 69632

__global__ __launch_bounds__(256, 3)
void istft_kernel(const float* __restrict__ xr,
                  const float* __restrict__ xi,
                  float* __restrict__ out)
{
    extern __shared__ __align__(16) char smem_raw[];
    float*  fr   = (float*)(smem_raw + OFF_FR);
    float2* win2 = (float2*)(smem_raw + OFF_WIN);
    float2* prt  = (float2*)(smem_raw + OFF_PRT);

    const int tid   = threadIdx.x;     // 256
    const int warp  = tid >> 5;
    const int lane  = tid & 31;
    const int group = blockIdx.x;
    const int batch = blockIdx.y;
    const int f0     = group * G;
    const int fstart = f0 - 3;

    // window pairs (natural order): win2[m] = (w[2m], w[2m+1]) / (1.5*512)
    {
        int m = tid;
        float w0 = (0.5f - 0.5f * cosf(2.0f * CUDART_PI_F * (float)(2 * m)     * (1.0f / 512.0f))) * (1.0f / 768.0f);
        float w1 = (0.5f - 0.5f * cosf(2.0f * CUDART_PI_F * (float)(2 * m + 1) * (1.0f / 512.0f))) * (1.0f / 768.0f);
        win2[m] = make_float2(w0, w1);
        float s, c;
        sincosf(CUDART_PI_F * (float)m * (1.0f / 256.0f), &s, &c);
        prt[m] = make_float2(c, s);
    }
    __syncthreads();

    // ---- per-lane twiddles (frame-invariant) ----
    float s128, c128; __sincosf(CUDART_PI_F * (float)lane * (1.0f / 128.0f), &s128, &c128);
    float s64,  c64;  __sincosf(CUDART_PI_F * (float)lane * (1.0f / 64.0f),  &s64,  &c64);
    float s32,  c32;  __sincosf(CUDART_PI_F * (float)lane * (1.0f / 32.0f),  &s32,  &c32);
    float s16,  c16;  __sincosf(CUDART_PI_F * (float)(lane & 15) * (1.0f / 16.0f), &s16, &c16);
    float s8t,  c8t;  __sincosf(CUDART_PI_F * (float)(lane & 7)  * (1.0f / 8.0f),  &s8t, &c8t);

    const float R2 = 0.70710678118654752f;
    float w128c[4], w128s[4];
    w128c[0] = c128;               w128s[0] = s128;
    w128c[1] = R2 * (c128 - s128); w128s[1] = R2 * (c128 + s128);
    w128c[2] = -s128;              w128s[2] = c128;
    w128c[3] = -R2 * (c128 + s128); w128s[3] = R2 * (c128 - s128);

    const int rl = (int)(__brev((unsigned)lane) >> 27);     // rev5(lane)
    const int msrc = (32 - lane) & 31;                      // mirror shuffle source
    const int wx = (lane >> 4) & 1;                         // transpose write xor (low bit)
    const int rx = (lane >> 1) & 15;                        // transpose read xor
    const size_t bbase = (size_t)batch * FRAMES;

    // branch-free constants for lane stages m = 16, 8
    const float sg16 = (lane & 16) ? -1.f : 1.f;
    const float W16c = (lane & 16) ? c16 : 1.f, W16s = (lane & 16) ? s16 : 0.f;
    const float sg8  = (lane & 8)  ? -1.f : 1.f;
    const float W8c  = (lane & 8)  ? c8t : 1.f, W8s  = (lane & 8)  ? s8t : 0.f;

    for (int lf = warp; lf < FRAMES_SH; lf += 8) {
        const int f = fstart + lf;
        float2* row2 = (float2*)(fr + lf * 512);

        if ((unsigned)f >= (unsigned)FRAMES) {
            #pragma unroll
            for (int q = 0; q < 8; q++) row2[(q << 5) + lane] = make_float2(0.f, 0.f);
            continue;
        }

        const float* pre = xr + (bbase + f) * BINS;
        const float* pim = xi + (bbase + f) * BINS;

        // ---- load each bin once: k = 32*j + lane (coalesced) ----
        float kr[8], ki[8];
        #pragma unroll
        for (int j = 0; j < 8; j++) {
            int k = 32 * j + lane;
            kr[j] = pre[k];
            ki[j] = pim[k];
        }
        const float pre256 = pre[256];

        float zr[8], zi[8];

        // Hermitian pack + pre-rotation; mirror X[256-k] via lane shuffle
        #pragma unroll
        for (int j = 0; j < 8; j++) {
            float br = __shfl_sync(0xffffffffu, kr[7 - j], msrc);
            float mi = __shfl_sync(0xffffffffu, ki[7 - j], msrc);
            if (lane == 0) {
                br = (j == 0) ? pre256 : kr[8 - j];
                mi = (j == 0) ? 0.f    : ki[8 - j];
            }
            float ar = kr[j];
            float ai = (j == 0 && lane == 0) ? 0.f : ki[j];
            float er = ar + br, ei = ai - mi;    // bi = -mi
            float dr = ar - br, di = ai + mi;
            float2 t = prt[32 * j + lane];       // (cos, sin) pi*k/256
            zr[j] = fmaf(-di, t.x, fmaf(-dr, t.y, er));
            zi[j] = fmaf(-di, t.y, fmaf( dr, t.x, ei));
        }

        // ---- register stages (h = 128, 64, 32) ----
        #pragma unroll
        for (int j = 0; j < 4; j++) {
            float tr = zr[j] - zr[j + 4], ti = zi[j] - zi[j + 4];
            zr[j] += zr[j + 4]; zi[j] += zi[j + 4];
            zr[j + 4] = tr * w128c[j] - ti * w128s[j];
            zi[j + 4] = tr * w128s[j] + ti * w128c[j];
        }
        #define RB(A,B,CC,SS) { float tr=zr[A]-zr[B], ti=zi[A]-zi[B]; \
            zr[A]+=zr[B]; zi[A]+=zi[B]; zr[B]=tr*(CC)-ti*(SS); zi[B]=tr*(SS)+ti*(CC); }
        RB(0, 2, c64, s64)  RB(4, 6, c64, s64)
        RB(1, 3, -s64, c64) RB(5, 7, -s64, c64)
        RB(0, 1, c32, s32) RB(2, 3, c32, s32)
        RB(4, 5, c32, s32) RB(6, 7, c32, s32)
        #undef RB

        // ---- lane stages (branch-free): m = 16, 8 ----
        #define LSTAGE(MASK, SG, WC, WS)                                        \
        {                                                                       \
            _Pragma("unroll")                                                   \
            for (int j = 0; j < 8; j++) {                                       \
                float orr = __shfl_xor_sync(0xffffffffu, zr[j], (MASK));        \
                float oii = __shfl_xor_sync(0xffffffffu, zi[j], (MASK));        \
                float tr = fmaf(zr[j], (SG), orr);                              \
                float ti = fmaf(zi[j], (SG), oii);                              \
                zr[j] = tr * (WC) - ti * (WS);                                  \
                zi[j] = tr * (WS) + ti * (WC);                                  \
            }                                                                   \
        }
        LSTAGE(16, sg16, W16c, W16s)
        LSTAGE(8,  sg8,  W8c,  W8s)
        #undef LSTAGE

        // ---- warp transpose through the frame's own row (swizzled) ----
        // write slot p = 32j + lane at addr p ^ ((j<<1)|wx)
        #pragma unroll
        for (int j = 0; j < 8; j++) {
            int a = (32 * j + lane) ^ ((j << 1) | wx);
            row2[a] = make_float2(zr[j], zi[j]);
        }
        __syncwarp(0xffffffffu);
        // read slot p = 8*lane + t at addr p ^ rx
        float vr[8], vi[8];
        #pragma unroll
        for (int t = 0; t < 8; t++) {
            float2 v = row2[(8 * lane + t) ^ rx];
            vr[t] = v.x; vi[t] = v.y;
        }
        __syncwarp(0xffffffffu);

        // ---- register stages d = 4, 2, 1 (constant twiddles) ----
        #define RB1(A,B) { float tr=vr[A]-vr[B], ti=vi[A]-vi[B]; \
            vr[A]+=vr[B]; vi[A]+=vi[B]; vr[B]=tr; vi[B]=ti; }
        #define RBI(A,B) { float tr=vr[A]-vr[B], ti=vi[A]-vi[B]; \
            vr[A]+=vr[B]; vi[A]+=vi[B]; vr[B]=-ti; vi[B]=tr; }
        #define RBC(A,B,CC,SS) { float tr=vr[A]-vr[B], ti=vi[A]-vi[B]; \
            vr[A]+=vr[B]; vi[A]+=vi[B]; vr[B]=tr*(CC)-ti*(SS); vi[B]=tr*(SS)+ti*(CC); }
        RB1(0, 4) RBC(1, 5, R2, R2) RBI(2, 6) RBC(3, 7, -R2, R2)
        RB1(0, 2) RBI(1, 3) RB1(4, 6) RBI(5, 7)
        RB1(0, 1) RB1(2, 3) RB1(4, 5) RB1(6, 7)
        #undef RB1
        #undef RBI
        #undef RBC

        // ---- final windowed store, natural order ----
        // reg t holds slot p = 8*lane + t -> z[n], n = 32*rev3(t) + rev5(lane)
        {
            const int rev3t[8] = {0, 4, 2, 6, 1, 5, 3, 7};
            #pragma unroll
            for (int t = 0; t < 8; t++) {
                int n = (rev3t[t] << 5) + rl;
                float2 w2 = win2[n];
                row2[n] = make_float2(vr[t] * w2.x, vi[t] * w2.y);
            }
        }
    }
    __syncthreads();

    // ---- gather overlap-add (natural layout; window already applied) ----
    const int sbase = f0 * HOP;
    const int owned = (group == NGROUPS - 1) ? (OUT_LEN - sbase) : (G * HOP);
    const int n4 = (owned + 3) >> 2;
    float* outb = out + (size_t)batch * OUT_LEN;
    for (int t = tid; t < n4; t += 256) {
        int s0 = 4 * t;
        int qf = s0 >> 7;
        int r4 = (s0 & 127) >> 2;
        float a0 = 0.f, a1 = 0.f, a2 = 0.f, a3 = 0.f;
        #pragma unroll
        for (int d = 0; d < 4; d++) {
            int lf = qf - d + 3;
            if (lf < FRAMES_SH) {
                float4 v = *(const float4*)&fr[lf * 512 + 4 * (r4 + (d << 5))];
                a0 += v.x; a1 += v.y; a2 += v.z; a3 += v.w;
            }
        }
        int S = sbase + s0;
        if (S + 3 < OUT_LEN) {
            outb[S] = a0; outb[S + 1] = a1; outb[S + 2] = a2; outb[S + 3] = a3;
        } else {
            if (S     < OUT_LEN) outb[S]     = a0;
            if (S + 1 < OUT_LEN) outb[S + 1] = a1;
            if (S + 2 < OUT_LEN) outb[S + 2] = a2;
        }
    }
}

extern "C" void kernel_launch(void* const* d_in, const int* in_sizes, int n_in,
                              void* d_out, int out_size)
{
    const float* stft_real = (const float*)d_in[0];
    const float* stft_imag = (const float*)d_in[1];
    float* out = (float*)d_out;
    (void)in_sizes; (void)n_in; (void)out_size;

    cudaFuncSetAttribute(istft_kernel,
                         cudaFuncAttributeMaxDynamicSharedMemorySize, SMEM_BYTES);
    dim3 grid(NGROUPS, BATCH);
    istft_kernel<<<grid, 256, SMEM_BYTES>>>(stft_real, stft_imag, out);
}

// round 10
// speedup vs baseline: 1.4178x; 1.1771x over previous
#include <cuda_runtime.h>
#include <math_constants.h>

#define BATCH     16
#define FRAMES    4000
#define BINS      257
#define HOP       128
#define G         29
#define NGROUPS   138
#define FRAMES_SH 32
#define OUT_LEN   512383

#define SMEM_BYTES (FRAMES_SH * 512 * 4)   // 65536: frame buffer only

__global__ __launch_bounds__(256, 3)
void istft_kernel(const float* __restrict__ xr,
                  const float* __restrict__ xi,
                  float* __restrict__ out)
{
    extern __shared__ __align__(16) char smem_raw[];
    float* fr = (float*)smem_raw;

    const int tid   = threadIdx.x;     // 256
    const int warp  = tid >> 5;
    const int lane  = tid & 31;
    const int group = blockIdx.x;
    const int batch = blockIdx.y;
    const int f0     = group * G;
    const int fstart = f0 - 3;

    // ---- per-lane twiddles (frame-invariant) ----
    float pls, plc;   __sincosf(CUDART_PI_F * (float)lane * (1.0f / 256.0f), &pls, &plc);  // prerot base
    float s128, c128; __sincosf(CUDART_PI_F * (float)lane * (1.0f / 128.0f), &s128, &c128);
    float s64,  c64;  __sincosf(CUDART_PI_F * (float)lane * (1.0f / 64.0f),  &s64,  &c64);
    float s32,  c32;  __sincosf(CUDART_PI_F * (float)lane * (1.0f / 32.0f),  &s32,  &c32);
    float s16,  c16;  __sincosf(CUDART_PI_F * (float)(lane & 15) * (1.0f / 16.0f), &s16, &c16);
    float s8t,  c8t;  __sincosf(CUDART_PI_F * (float)(lane & 7)  * (1.0f / 8.0f),  &s8t, &c8t);

    const float R2 = 0.70710678118654752f;
    float w128c[4], w128s[4];
    w128c[0] = c128;               w128s[0] = s128;
    w128c[1] = R2 * (c128 - s128); w128s[1] = R2 * (c128 + s128);
    w128c[2] = -s128;              w128s[2] = c128;
    w128c[3] = -R2 * (c128 + s128); w128s[3] = R2 * (c128 - s128);

    // prerot per-j constants e^{i*pi*j/8}
    const float C8[8] = {1.f, 0.92387953251128674f, 0.70710678118654752f, 0.38268343236508977f,
                         0.f, -0.38268343236508977f, -0.70710678118654752f, -0.92387953251128674f};
    const float S8[8] = {0.f, 0.38268343236508977f, 0.70710678118654752f, 0.92387953251128674f,
                         1.f, 0.92387953251128674f, 0.70710678118654752f, 0.38268343236508977f};

    const int rl = (int)(__brev((unsigned)lane) >> 27);     // rev5(lane)
    const int msrc = (32 - lane) & 31;                      // mirror shuffle source
    const int wx = (lane >> 4) & 1;                         // transpose write xor (low bit)
    const int rx = (lane >> 1) & 15;                        // transpose read xor
    const size_t bbase = (size_t)batch * FRAMES;

    // window-in-registers: w(64a + b) = K' - K'*cos(pi*a/4 + theta_b), b = 2rl or 2rl+1
    const float KP = 1.0f / 1536.0f;                        // 0.5 / 768
    float th0s, th0c; __sincosf(CUDART_PI_F * (float)(2 * rl)     * (1.0f / 256.0f), &th0s, &th0c);
    float th1s, th1c; __sincosf(CUDART_PI_F * (float)(2 * rl + 1) * (1.0f / 256.0f), &th1s, &th1c);
    const float Kc0 = KP * th0c, Ks0 = KP * th0s;
    const float Kc1 = KP * th1c, Ks1 = KP * th1s;
    // cos/sin(pi*a/4) immediates
    const float CA[8] = {1.f,  R2, 0.f, -R2, -1.f, -R2, 0.f,  R2};
    const float SA[8] = {0.f,  R2, 1.f,  R2, 0.f,  -R2, -1.f, -R2};

    // branch-free constants for lane stages m = 16, 8
    const float sg16 = (lane & 16) ? -1.f : 1.f;
    const float W16c = (lane & 16) ? c16 : 1.f, W16s = (lane & 16) ? s16 : 0.f;
    const float sg8  = (lane & 8)  ? -1.f : 1.f;
    const float W8c  = (lane & 8)  ? c8t : 1.f, W8s  = (lane & 8)  ? s8t : 0.f;

    for (int lf = warp; lf < FRAMES_SH; lf += 8) {
        const int f = fstart + lf;
        float2* row2 = (float2*)(fr + lf * 512);

        if ((unsigned)f >= (unsigned)FRAMES) {
            #pragma unroll
            for (int q = 0; q < 8; q++) row2[(q << 5) + lane] = make_float2(0.f, 0.f);
            continue;
        }

        const float* pre = xr + (bbase + f) * BINS;
        const float* pim = xi + (bbase + f) * BINS;

        // ---- load each bin once: k = 32*j + lane (coalesced) ----
        float kr[8], ki[8];
        #pragma unroll
        for (int j = 0; j < 8; j++) {
            int k = 32 * j + lane;
            kr[j] = pre[k];
            ki[j] = pim[k];
        }
        const float pre256 = pre[256];

        float zr[8], zi[8];

        // Hermitian pack + pre-rotation (registers only); mirror via lane shuffle
        #pragma unroll
        for (int j = 0; j < 8; j++) {
            float br = __shfl_sync(0xffffffffu, kr[7 - j], msrc);
            float mi = __shfl_sync(0xffffffffu, ki[7 - j], msrc);
            if (lane == 0) {
                br = (j == 0) ? pre256 : kr[8 - j];
                mi = (j == 0) ? 0.f    : ki[8 - j];
            }
            float ar = kr[j];
            float ai = (j == 0 && lane == 0) ? 0.f : ki[j];
            float er = ar + br, ei = ai - mi;    // bi = -mi
            float dr = ar - br, di = ai + mi;
            // prerot e^{i*pi*k/256} = (plc,pls) * (C8[j],S8[j])
            float pc = plc * C8[j] - pls * S8[j];
            float ps = plc * S8[j] + pls * C8[j];
            zr[j] = fmaf(-di, pc, fmaf(-dr, ps, er));   // er - dr*s - di*c
            zi[j] = fmaf(-di, ps, fmaf( dr, pc, ei));   // ei + dr*c - di*s
        }

        // ---- register stages (h = 128, 64, 32) ----
        #pragma unroll
        for (int j = 0; j < 4; j++) {
            float tr = zr[j] - zr[j + 4], ti = zi[j] - zi[j + 4];
            zr[j] += zr[j + 4]; zi[j] += zi[j + 4];
            zr[j + 4] = tr * w128c[j] - ti * w128s[j];
            zi[j + 4] = tr * w128s[j] + ti * w128c[j];
        }
        #define RB(A,B,CC,SS) { float tr=zr[A]-zr[B], ti=zi[A]-zi[B]; \
            zr[A]+=zr[B]; zi[A]+=zi[B]; zr[B]=tr*(CC)-ti*(SS); zi[B]=tr*(SS)+ti*(CC); }
        RB(0, 2, c64, s64)  RB(4, 6, c64, s64)
        RB(1, 3, -s64, c64) RB(5, 7, -s64, c64)
        RB(0, 1, c32, s32) RB(2, 3, c32, s32)
        RB(4, 5, c32, s32) RB(6, 7, c32, s32)
        #undef RB

        // ---- lane stages (branch-free): m = 16, 8 ----
        #define LSTAGE(MASK, SG, WC, WS)                                        \
        {                                                                       \
            _Pragma("unroll")                                                   \
            for (int j = 0; j < 8; j++) {                                       \
                float orr = __shfl_xor_sync(0xffffffffu, zr[j], (MASK));        \
                float oii = __shfl_xor_sync(0xffffffffu, zi[j], (MASK));        \
                float tr = fmaf(zr[j], (SG), orr);                              \
                float ti = fmaf(zi[j], (SG), oii);                              \
                zr[j] = tr * (WC) - ti * (WS);                                  \
                zi[j] = tr * (WS) + ti * (WC);                                  \
            }                                                                   \
        }
        LSTAGE(16, sg16, W16c, W16s)
        LSTAGE(8,  sg8,  W8c,  W8s)
        #undef LSTAGE

        // ---- warp transpose through the frame's own row (swizzled) ----
        #pragma unroll
        for (int j = 0; j < 8; j++) {
            int a = (32 * j + lane) ^ ((j << 1) | wx);
            row2[a] = make_float2(zr[j], zi[j]);
        }
        __syncwarp(0xffffffffu);
        float vr[8], vi[8];
        #pragma unroll
        for (int t = 0; t < 8; t++) {
            float2 v = row2[(8 * lane + t) ^ rx];
            vr[t] = v.x; vi[t] = v.y;
        }
        __syncwarp(0xffffffffu);

        // ---- register stages d = 4, 2, 1 (constant twiddles) ----
        #define RB1(A,B) { float tr=vr[A]-vr[B], ti=vi[A]-vi[B]; \
            vr[A]+=vr[B]; vi[A]+=vi[B]; vr[B]=tr; vi[B]=ti; }
        #define RBI(A,B) { float tr=vr[A]-vr[B], ti=vi[A]-vi[B]; \
            vr[A]+=vr[B]; vi[A]+=vi[B]; vr[B]=-ti; vi[B]=tr; }
        #define RBC(A,B,CC,SS) { float tr=vr[A]-vr[B], ti=vi[A]-vi[B]; \
            vr[A]+=vr[B]; vi[A]+=vi[B]; vr[B]=tr*(CC)-ti*(SS); vi[B]=tr*(SS)+ti*(CC); }
        RB1(0, 4) RBC(1, 5, R2, R2) RBI(2, 6) RBC(3, 7, -R2, R2)
        RB1(0, 2) RBI(1, 3) RB1(4, 6) RBI(5, 7)
        RB1(0, 1) RB1(2, 3) RB1(4, 5) RB1(6, 7)
        #undef RB1
        #undef RBI
        #undef RBC

        // ---- final windowed store, natural order; window from registers ----
        // reg t holds z[m], m = 32*rev3(t) + rl -> time samples 2m, 2m+1
        {
            const int rev3t[8] = {0, 4, 2, 6, 1, 5, 3, 7};
            #pragma unroll
            for (int t = 0; t < 8; t++) {
                int a = rev3t[t];
                float w0 = fmaf(SA[a], Ks0, fmaf(-CA[a], Kc0, KP));
                float w1 = fmaf(SA[a], Ks1, fmaf(-CA[a], Kc1, KP));
                int n = (a << 5) + rl;
                row2[n] = make_float2(vr[t] * w0, vi[t] * w1);
            }
        }
    }
    __syncthreads();

    // ---- gather overlap-add (natural layout; window already applied) ----
    const int sbase = f0 * HOP;
    const int owned = (group == NGROUPS - 1) ? (OUT_LEN - sbase) : (G * HOP);
    const int n4 = (owned + 3) >> 2;
    float* outb = out + (size_t)batch * OUT_LEN;
    for (int t = tid; t < n4; t += 256) {
        int s0 = 4 * t;
        int qf = s0 >> 7;
        int r4 = (s0 & 127) >> 2;
        float a0 = 0.f, a1 = 0.f, a2 = 0.f, a3 = 0.f;
        #pragma unroll
        for (int d = 0; d < 4; d++) {
            int lf = qf - d + 3;
            if (lf < FRAMES_SH) {
                float4 v = *(const float4*)&fr[lf * 512 + 4 * (r4 + (d << 5))];
                a0 += v.x; a1 += v.y; a2 += v.z; a3 += v.w;
            }
        }
        int S = sbase + s0;
        if (S + 3 < OUT_LEN) {
            outb[S] = a0; outb[S + 1] = a1; outb[S + 2] = a2; outb[S + 3] = a3;
        } else {
            if (S     < OUT_LEN) outb[S]     = a0;
            if (S + 1 < OUT_LEN) outb[S + 1] = a1;
            if (S + 2 < OUT_LEN) outb[S + 2] = a2;
        }
    }
}

extern "C" void kernel_launch(void* const* d_in, const int* in_sizes, int n_in,
                              void* d_out, int out_size)
{
    const float* stft_real = (const float*)d_in[0];
    const float* stft_imag = (const float*)d_in[1];
    float* out = (float*)d_out;
    (void)in_sizes; (void)n_in; (void)out_size;

    cudaFuncSetAttribute(istft_kernel,
                         cudaFuncAttributeMaxDynamicSharedMemorySize, SMEM_BYTES);
    dim3 grid(NGROUPS, BATCH);
    istft_kernel<<<grid, 256, SMEM_BYTES>>>(stft_real, stft_imag, out);
}